// round 1
// baseline (speedup 1.0000x reference)
#include <cuda_runtime.h>
#include <cstdint>

#define BB 64          // batch
#define CC 4096        // capsules
#define IND 512        // in_dim (K)
#define OO 16          // caps_len (N)
#define TI 32          // i-tile staged in smem
#define NTILES (IND / TI)   // 16
#define NTH 64         // threads per CTA (one capsule per CTA)

// ---- packed f32x2 helpers (sm_100+ PTX) ----
__device__ __forceinline__ uint64_t pack_dup(float x) {
    uint64_t r;
    asm("mov.b64 %0, {%1, %1};" : "=l"(r) : "f"(x));
    return r;
}
__device__ __forceinline__ void fma2(uint64_t& d, uint64_t a, uint64_t b) {
    asm("fma.rn.f32x2 %0, %1, %2, %0;" : "+l"(d) : "l"(a), "l"(b));
}
__device__ __forceinline__ void unpack2(uint64_t v, float& lo, float& hi) {
    asm("mov.b64 {%0, %1}, %2;" : "=f"(lo), "=f"(hi) : "l"(v));
}

__global__ __launch_bounds__(NTH)
void primarycaps_kernel(const float* __restrict__ x,
                        const float* __restrict__ W,
                        const float* __restrict__ bias,
                        float* __restrict__ out)
{
    __shared__ float sW[IND * OO];     // 32 KB: W[c] in original [i][o] layout
    __shared__ float sX[BB * TI];      // 8 KB: x tile, XOR-swizzled rows

    const int c  = blockIdx.x;
    const int t  = threadIdx.x;
    const int bg = t & 31;             // lane within warp -> b row group
    const int og = t >> 5;             // warp id -> o half
    const int o0 = og * 8;

    // ---- load W[c] into smem (coalesced, one-time) ----
    {
        const float4* Wg  = (const float4*)(W + (size_t)c * IND * OO);
        float4*       Ws4 = (float4*)sW;
        #pragma unroll
        for (int k = 0; k < (IND * OO / 4) / NTH; ++k)
            Ws4[t + k * NTH] = Wg[t + k * NTH];
    }

    // accumulators: 2 b-rows x 4 o-pairs, each uint64 = packed (f32,f32)
    uint64_t acc[2][4];
    #pragma unroll
    for (int i = 0; i < 2; ++i)
        #pragma unroll
        for (int j = 0; j < 4; ++j)
            acc[i][j] = 0ULL;          // bit pattern of (0.f, 0.f)

    // ---- staging mapping: lane -> (row group, float4 within 32-float row) ----
    const int sb   = t >> 3;           // 0..7
    const int sii4 = t & 7;            // 0..7
    const float* xg_base = x + ((size_t)sb * CC + c) * IND + sii4 * 4;

    float4 xr[8];                      // register prefetch buffer (one tile)

    // prefetch tile 0
    #pragma unroll
    for (int k = 0; k < 8; ++k)
        xr[k] = *(const float4*)(xg_base + (size_t)k * 8 * CC * IND);

    for (int tile = 0; tile < NTILES; ++tile) {
        __syncthreads();               // previous tile fully consumed

        // store prefetched tile into swizzled smem (bank-conflict-free)
        #pragma unroll
        for (int k = 0; k < 8; ++k) {
            const int b    = sb + k * 8;
            const int base = b * TI;
            const int s    = b & 31;
            const int ii   = sii4 * 4;
            sX[base + ((ii + 0) ^ s)] = xr[k].x;
            sX[base + ((ii + 1) ^ s)] = xr[k].y;
            sX[base + ((ii + 2) ^ s)] = xr[k].z;
            sX[base + ((ii + 3) ^ s)] = xr[k].w;
        }
        __syncthreads();

        // prefetch next tile (LDG latency hidden behind compute below)
        if (tile + 1 < NTILES) {
            const float* xg = xg_base + (size_t)(tile + 1) * TI;
            #pragma unroll
            for (int k = 0; k < 8; ++k)
                xr[k] = *(const float4*)(xg + (size_t)k * 8 * CC * IND);
        }

        // ---- compute tile: 32 i-steps, 16 FMA ops each (8 FFMA2) ----
        const int i0 = tile * TI;
        #pragma unroll 8
        for (int ii = 0; ii < TI; ++ii) {
            // x reads: scalar, swizzled, conflict-free across the warp
            const float xv0 = sX[bg * TI + (ii ^ bg)];
            const float xv1 = sX[(bg + 32) * TI + (ii ^ bg)];
            const uint64_t xd0 = pack_dup(xv0);
            const uint64_t xd1 = pack_dup(xv1);

            // W row: 8 consecutive o's = 4 packed f32x2 pairs (broadcast LDS)
            const ulonglong2* wr =
                (const ulonglong2*)(sW + (i0 + ii) * OO + o0);
            const ulonglong2 wA = wr[0];   // o0..o0+3
            const ulonglong2 wB = wr[1];   // o0+4..o0+7

            fma2(acc[0][0], xd0, wA.x);
            fma2(acc[0][1], xd0, wA.y);
            fma2(acc[0][2], xd0, wB.x);
            fma2(acc[0][3], xd0, wB.y);
            fma2(acc[1][0], xd1, wA.x);
            fma2(acc[1][1], xd1, wA.y);
            fma2(acc[1][2], xd1, wB.x);
            fma2(acc[1][3], xd1, wB.y);
        }
    }

    // ---- epilogue: unpack, add bias, vector store ----
    const float4* bias4 = (const float4*)(bias + (size_t)c * OO + o0);
    const float4 bz0 = bias4[0];
    const float4 bz1 = bias4[1];

    #pragma unroll
    for (int r = 0; r < 2; ++r) {
        float v0, v1, v2, v3, v4, v5, v6, v7;
        unpack2(acc[r][0], v0, v1);
        unpack2(acc[r][1], v2, v3);
        unpack2(acc[r][2], v4, v5);
        unpack2(acc[r][3], v6, v7);

        float4 lo = make_float4(v0 + bz0.x, v1 + bz0.y, v2 + bz0.z, v3 + bz0.w);
        float4 hi = make_float4(v4 + bz1.x, v5 + bz1.y, v6 + bz1.z, v7 + bz1.w);

        const int b = bg + r * 32;
        float* op = out + ((size_t)b * CC + c) * OO + o0;
        *(float4*)(op)     = lo;
        *(float4*)(op + 4) = hi;
    }
}

extern "C" void kernel_launch(void* const* d_in, const int* in_sizes, int n_in,
                              void* d_out, int out_size)
{
    (void)in_sizes; (void)n_in; (void)out_size;
    const float* x    = (const float*)d_in[0];
    const float* W    = (const float*)d_in[1];
    const float* bias = (const float*)d_in[2];
    float*       out  = (float*)d_out;

    primarycaps_kernel<<<CC, NTH>>>(x, W, bias, out);
}